// round 16
// baseline (speedup 1.0000x reference)
#include <cuda_runtime.h>
#include <cuda_bf16.h>
#include <cstdint>

#define M_MATCH 5000
#define TOT     10000
#define CF      128
#define CC      256
#define WW      25
#define LCELLS  4800
#define HFD     240
#define WFD     320
#define CHW     (CF * HFD * WFD)
#define G_TOTAL 250000
#define TILES   1954                 // ceil(250000/128)

typedef unsigned long long ull;

__device__ float g_t[TOT * CF];
__device__ float g_Wc[CC * CF];
__device__ float g_bc[CF];

__device__ __forceinline__ uint32_t smem_u32(const void* p) {
    uint32_t a;
    asm("{ .reg .u64 t; cvta.to.shared.u64 t, %1; cvt.u32.u64 %0, t; }" : "=r"(a) : "l"(p));
    return a;
}

#define LDSM_X4(r0, r1, r2, r3, addr)                                          \
    asm volatile("ldmatrix.sync.aligned.m8n8.x4.shared.b16 {%0,%1,%2,%3}, [%4];" \
        : "=r"(r0), "=r"(r1), "=r"(r2), "=r"(r3) : "r"(addr))

#define MMA16816(d, a0, a1, a2, a3, b0, b1)                                    \
    asm volatile("mma.sync.aligned.m16n8k16.row.col.f32.bf16.bf16.f32 "        \
        "{%0,%1,%2,%3}, {%4,%5,%6,%7}, {%8,%9}, {%0,%1,%2,%3};"                \
        : "+f"((d)[0]), "+f"((d)[1]), "+f"((d)[2]), "+f"((d)[3])               \
        : "r"(a0), "r"(a1), "r"(a2), "r"(a3), "r"(b0), "r"(b1))

#define CP_ASYNC4(dst, src, sz)                                                \
    asm volatile("cp.async.ca.shared.global [%0], [%1], 4, %2;"                \
        :: "r"(dst), "l"(src), "r"(sz) : "memory")
#define CP_COMMIT() asm volatile("cp.async.commit_group;" ::: "memory")
#define CP_WAIT0()  asm volatile("cp.async.wait_group 0;" ::: "memory")

__global__ void warmup_kernel() {}

// ---------------------------------------------------------------------------
// Kernel 0: Wc[c][o] = sum_j Wd[j][c]*W2[o][j];  bc = W2@bd + bm
// ---------------------------------------------------------------------------
__global__ void __launch_bounds__(128)
wc_kernel(const float* __restrict__ Wd, const float* __restrict__ bd,
          const float* __restrict__ Wm, const float* __restrict__ bm)
{
    extern __shared__ float w2T[];   // [j][129]
    const int tid = threadIdx.x;
    const int c = blockIdx.x;

    for (int it = 0; it < 128; it++)
        w2T[tid * 129 + it] = Wm[it * 256 + 128 + tid];
    __syncthreads();

    float a0 = 0.f, a1 = 0.f;
    #pragma unroll 4
    for (int j = 0; j < 128; j++) {
        float w2 = w2T[j * 129 + tid];
        a0 += __ldg(&Wd[j * 256 + c])       * w2;
        a1 += __ldg(&Wd[j * 256 + c + 128]) * w2;
    }
    g_Wc[(size_t)c * 128 + tid]         = a0;
    g_Wc[(size_t)(c + 128) * 128 + tid] = a1;

    if (blockIdx.x == 0) {
        float acc = bm[tid];
        #pragma unroll 4
        for (int j = 0; j < 128; j++)
            acc += w2T[j * 129 + tid] * __ldg(&bd[j]);
        g_bc[tid] = acc;
    }
}

// ---------------------------------------------------------------------------
// Kernel 1: t = gather(feat_c) @ Wc + bc.  (unchanged, verified)
// ---------------------------------------------------------------------------
#define PTILE 32
#define NPTILES ((TOT + PTILE - 1) / PTILE)

__global__ void __launch_bounds__(256, 2)
proj_kernel(const float* __restrict__ feat_c0, const float* __restrict__ feat_c1,
            const int* __restrict__ b_ids, const int* __restrict__ i_ids,
            const int* __restrict__ j_ids)
{
    extern __shared__ char sraw[];
    float* A   = (float*)sraw;
    float* Wcs = (float*)(sraw + 8192);
    const float** srow = (const float**)(sraw + 8192 + 32768);

    const int tid = threadIdx.x;
    const int tile = blockIdx.x;
    const int og = tid & 15, rg = tid >> 4;
    const int o0 = og * 8;

    if (tid < PTILE) {
        int m = tile * PTILE + tid;
        const float* p = nullptr;
        if (m < TOT) {
            int mm = (m < M_MATCH) ? m : m - M_MATCH;
            int b  = b_ids[mm];
            int l  = (m < M_MATCH) ? i_ids[mm] : j_ids[mm];
            p = ((m < M_MATCH) ? feat_c0 : feat_c1) + ((size_t)b * LCELLS + l) * CC;
        }
        srow[tid] = p;
    }

    float acc[2][8];
    {
        float4 bA = *(const float4*)&g_bc[o0];
        float4 bB = *(const float4*)&g_bc[o0 + 4];
        #pragma unroll
        for (int j = 0; j < 2; j++) {
            acc[j][0] = bA.x; acc[j][1] = bA.y; acc[j][2] = bA.z; acc[j][3] = bA.w;
            acc[j][4] = bB.x; acc[j][5] = bB.y; acc[j][6] = bB.z; acc[j][7] = bB.w;
        }
    }
    __syncthreads();

    for (int kc = 0; kc < 256; kc += 64) {
        for (int e = tid; e < 32 * 64; e += 256) {
            const float* p = srow[e >> 6];
            A[e] = p ? __ldg(p + kc + (e & 63)) : 0.f;
        }
        for (int e = tid; e < 64 * 128; e += 256)
            Wcs[e] = g_Wc[(size_t)(kc + (e >> 7)) * 128 + (e & 127)];
        __syncthreads();

        #pragma unroll 2
        for (int k = 0; k < 64; k += 4) {
            float4 fv[2];
            #pragma unroll
            for (int j = 0; j < 2; j++)
                fv[j] = *(const float4*)&A[(rg + 16 * j) * 64 + k];
            #define PSTEP(kk, COMP)                                            \
            {                                                                  \
                float4 wA = *(const float4*)&Wcs[(k + kk) * 128 + o0];         \
                float4 wB = *(const float4*)&Wcs[(k + kk) * 128 + o0 + 4];     \
                _Pragma("unroll")                                              \
                for (int j = 0; j < 2; j++) {                                  \
                    float a = fv[j].COMP;                                      \
                    acc[j][0] += a * wA.x; acc[j][1] += a * wA.y;              \
                    acc[j][2] += a * wA.z; acc[j][3] += a * wA.w;              \
                    acc[j][4] += a * wB.x; acc[j][5] += a * wB.y;              \
                    acc[j][6] += a * wB.z; acc[j][7] += a * wB.w;              \
                }                                                              \
            }
            PSTEP(0, x) PSTEP(1, y) PSTEP(2, z) PSTEP(3, w)
            #undef PSTEP
        }
        __syncthreads();
    }

    #pragma unroll
    for (int j = 0; j < 2; j++) {
        int m = tile * PTILE + rg + 16 * j;
        if (m < TOT) {
            float* dst = &g_t[(size_t)m * CF + o0];
            *(float4*)dst       = make_float4(acc[j][0], acc[j][1], acc[j][2], acc[j][3]);
            *(float4*)(dst + 4) = make_float4(acc[j][4], acc[j][5], acc[j][6], acc[j][7]);
        }
    }
}

// ---------------------------------------------------------------------------
// Kernel 2: fine — 128-row dense tiles, 32x32 warp tiles, cp.async overlap.
// ---------------------------------------------------------------------------
#define OFF_BH   0                      // 128 x 272 = 34816
#define OFF_BL   34816
#define OFF_AH   69632
#define OFF_AL   104448
#define OFF_STG  139264                 // 16384 f32 = 65536
#define OFF_TS   204800                 // 2 x 1024 f32 = 8192
#define SMEM_FINE 212992

__device__ __forceinline__ void decode_flat(unsigned flat, int& pos, int& p80,
                                            int& row, int& col, int& off)
{
    unsigned ch = flat / 120000u;
    unsigned r1 = flat - ch * 120000u;
    unsigned kk = r1 / 4800u;
    unsigned pp = r1 - kk * 4800u;
    int kh = (int)(kk / 5u);
    int kw = (int)(kk - 5u * (unsigned)kh);
    unsigned oh = pp / 80u;
    p80 = (int)(pp - 80u * oh);
    pos = (int)pp;
    row = (int)oh * 4 + kh - 2;
    col = p80 * 4 + kw - 2;
    off = (int)ch * 76800 + row * 320 + col;
}

// Issue gather (128 rows x 128 c) + t-prefetch for tile t2. Always commits.
__device__ __forceinline__ void issue_tile(
    uint32_t stg_sm, uint32_t ts_sm, int t2,
    const float* __restrict__ f0, const float* __restrict__ f1,
    const int* __restrict__ b_ids, const int* __restrict__ i_ids,
    const int* __restrict__ j_ids,
    int tid, int wid, int lane)
{
    if (t2 < TILES) {
        const int g0 = t2 * 128;
        #pragma unroll
        for (int rr = 0; rr < 8; rr++) {
            const int r = wid * 8 + rr;
            const int g = g0 + r;
            uint32_t dst = stg_sm + (uint32_t)(r * 128 + lane) * 4;
            if (g < G_TOTAL) {
                const int m  = g / 25;
                const int w  = g - m * 25;
                const int mm = (m < M_MATCH) ? m : m - M_MATCH;
                const int b  = __ldg(&b_ids[mm]);
                const int l  = (m < M_MATCH) ? __ldg(&i_ids[mm]) : __ldg(&j_ids[mm]);
                const float* fb = ((m < M_MATCH) ? f0 : f1) + (size_t)b * CHW;
                unsigned flat = (unsigned)l * 3200u + (unsigned)(w * 128 + lane);
                int pos, p80, row, col, off;
                decode_flat(flat, pos, p80, row, col, off);
                #pragma unroll
                for (int q = 0; q < 4; q++) {
                    const bool valid = ((row | col) >= 0);
                    const float* src = valid ? (fb + off) : fb;
                    CP_ASYNC4(dst, src, valid ? 4u : 0u);
                    dst += 128;
                    if (q < 3) {
                        flat += 32; pos += 32; p80 += 32; col += 128; off += 128;
                        if (pos >= 4800) {
                            decode_flat(flat, pos, p80, row, col, off);
                        } else if (p80 >= 80) {
                            p80 -= 80; row += 4; col -= 320; off += 960;
                        }
                    }
                }
            } else {
                const float* fb = f0;
                #pragma unroll
                for (int q = 0; q < 4; q++) { CP_ASYNC4(dst, fb, 0u); dst += 128; }
            }
        }
        // t prefetch: 8 matches from mb (1024 floats)
        const int mb = g0 / 25;
        #pragma unroll
        for (int it = 0; it < 2; it++) {
            int e = tid + it * 512;
            int m2 = mb + (e >> 7);
            const float* src = (m2 < TOT) ? &g_t[(size_t)m2 * CF + (e & 127)] : &g_t[0];
            CP_ASYNC4(ts_sm + (uint32_t)e * 4, src, (m2 < TOT) ? 4u : 0u);
        }
    }
    CP_COMMIT();
}

__global__ void __launch_bounds__(512, 1)
fine_kernel(const float* __restrict__ feat_f0, const float* __restrict__ feat_f1,
            const int* __restrict__ b_ids, const int* __restrict__ i_ids,
            const int* __restrict__ j_ids,
            const float* __restrict__ Wm, float* __restrict__ out)
{
    extern __shared__ char sraw[];
    char* Bh = sraw + OFF_BH;
    char* Bl = sraw + OFF_BL;
    char* Ah = sraw + OFF_AH;
    char* Al = sraw + OFF_AL;
    float* stg = (float*)(sraw + OFF_STG);
    float* ts0 = (float*)(sraw + OFF_TS);

    const uint32_t sBh = smem_u32(Bh);
    const uint32_t sBl = smem_u32(Bl);
    const uint32_t sAh = smem_u32(Ah);
    const uint32_t sAl = smem_u32(Al);
    const uint32_t sStg = smem_u32(stg);
    const uint32_t sTs  = smem_u32(ts0);

    const int tid  = threadIdx.x;
    const int wid  = tid >> 5;
    const int lane = tid & 31;
    const int grid = gridDim.x;

    // B prep: W1 = merge_w[:, :128], hi/lo split
    for (int e2 = tid; e2 < 8192; e2 += 512) {
        int o = e2 >> 6;
        int c = (e2 & 63) * 2;
        float v0 = Wm[o * 256 + c];
        float v1 = Wm[o * 256 + c + 1];
        __nv_bfloat16 h0 = __float2bfloat16(v0);
        __nv_bfloat16 h1 = __float2bfloat16(v1);
        __nv_bfloat16 l0 = __float2bfloat16(v0 - __bfloat162float(h0));
        __nv_bfloat16 l1 = __float2bfloat16(v1 - __bfloat162float(h1));
        __nv_bfloat162 hp, lp; hp.x = h0; hp.y = h1; lp.x = l0; lp.y = l1;
        *(uint32_t*)(Bh + o * 272 + c * 2) = *(uint32_t*)&hp;
        *(uint32_t*)(Bl + o * 272 + c * 2) = *(uint32_t*)&lp;
    }

    // warp grid: 4 row groups of 32 x 4 col groups of 32
    const int rbase = (wid & 3) * 32;
    const int cbase = (wid >> 2) * 32;
    const uint32_t aRow  = (uint32_t)(rbase + (lane & 15));
    const uint32_t aColB = (uint32_t)((lane >> 4) * 16);
    const uint32_t bRow  = (uint32_t)(cbase + (lane & 7) + ((lane >> 4) << 3));
    const uint32_t bColB = (uint32_t)(((lane >> 3) & 1) * 16);
    const int rl = lane >> 2;
    const int cl = 2 * (lane & 3);

    __syncthreads();
    issue_tile(sStg, sTs, (int)blockIdx.x,
               feat_f0, feat_f1, b_ids, i_ids, j_ids, tid, wid, lane);

    int i = 0;
    for (int tile = blockIdx.x; tile < TILES; tile += grid, i++) {
        CP_WAIT0();
        __syncthreads();                  // stg + ts[i&1] ready; A free

        // convert stg -> Ah/Al (truncation hi + residual lo, PRMT pack)
        #pragma unroll
        for (int it = 0; it < 8; it++) {
            int e4 = tid + (it << 9);     // 0..4095, 4 elems each
            int r = e4 >> 5, cq = e4 & 31;
            uint4 u = *(const uint4*)&stg[r * 128 + cq * 4];
            uint32_t h0 = u.x & 0xFFFF0000u;
            uint32_t h1 = u.y & 0xFFFF0000u;
            uint32_t h2 = u.z & 0xFFFF0000u;
            uint32_t h3 = u.w & 0xFFFF0000u;
            float l0 = __uint_as_float(u.x) - __uint_as_float(h0);
            float l1 = __uint_as_float(u.y) - __uint_as_float(h1);
            float l2 = __uint_as_float(u.z) - __uint_as_float(h2);
            float l3 = __uint_as_float(u.w) - __uint_as_float(h3);
            uint2 hp, lp;
            hp.x = __byte_perm(u.x, u.y, 0x7632);
            hp.y = __byte_perm(u.z, u.w, 0x7632);
            lp.x = __byte_perm(__float_as_uint(l0), __float_as_uint(l1), 0x7632);
            lp.y = __byte_perm(__float_as_uint(l2), __float_as_uint(l3), 0x7632);
            *(uint2*)(Ah + r * 272 + cq * 8) = hp;
            *(uint2*)(Al + r * 272 + cq * 8) = lp;
        }
        __syncthreads();                  // A ready; stg free

        issue_tile(sStg, sTs + (uint32_t)((i + 1) & 1) * 4096, tile + grid,
                   feat_f0, feat_f1, b_ids, i_ids, j_ids, tid, wid, lane);

        // ---- MMA: 3 terms x 8 k-steps, warp tile 32x32 ----
        float acc[2][4][4];
        #pragma unroll
        for (int a2 = 0; a2 < 2; a2++)
            #pragma unroll
            for (int nb = 0; nb < 4; nb++) {
                acc[a2][nb][0] = 0.f; acc[a2][nb][1] = 0.f;
                acc[a2][nb][2] = 0.f; acc[a2][nb][3] = 0.f;
            }

        #pragma unroll 1
        for (int ks = 0; ks < 8; ks++) {
            const uint32_t kb = (uint32_t)(ks * 32);
            uint32_t ah0_0, ah0_1, ah0_2, ah0_3, ah1_0, ah1_1, ah1_2, ah1_3;
            uint32_t al0_0, al0_1, al0_2, al0_3, al1_0, al1_1, al1_2, al1_3;
            uint32_t bfr[4][2];

            LDSM_X4(ah0_0, ah0_1, ah0_2, ah0_3, sAh + aRow * 272 + kb + aColB);
            LDSM_X4(ah1_0, ah1_1, ah1_2, ah1_3, sAh + (aRow + 16) * 272 + kb + aColB);
            #pragma unroll
            for (int bb = 0; bb < 2; bb++)
                LDSM_X4(bfr[2*bb][0], bfr[2*bb][1], bfr[2*bb+1][0], bfr[2*bb+1][1],
                        sBh + (bRow + bb * 16) * 272 + kb + bColB);
            #pragma unroll
            for (int nb = 0; nb < 4; nb++) {
                MMA16816(acc[0][nb], ah0_0, ah0_1, ah0_2, ah0_3, bfr[nb][0], bfr[nb][1]);
                MMA16816(acc[1][nb], ah1_0, ah1_1, ah1_2, ah1_3, bfr[nb][0], bfr[nb][1]);
            }
            LDSM_X4(al0_0, al0_1, al0_2, al0_3, sAl + aRow * 272 + kb + aColB);
            LDSM_X4(al1_0, al1_1, al1_2, al1_3, sAl + (aRow + 16) * 272 + kb + aColB);
            #pragma unroll
            for (int nb = 0; nb < 4; nb++) {
                MMA16816(acc[0][nb], al0_0, al0_1, al0_2, al0_3, bfr[nb][0], bfr[nb][1]);
                MMA16816(acc[1][nb], al1_0, al1_1, al1_2, al1_3, bfr[nb][0], bfr[nb][1]);
            }
            #pragma unroll
            for (int bb = 0; bb < 2; bb++)
                LDSM_X4(bfr[2*bb][0], bfr[2*bb][1], bfr[2*bb+1][0], bfr[2*bb+1][1],
                        sBl + (bRow + bb * 16) * 272 + kb + bColB);
            #pragma unroll
            for (int nb = 0; nb < 4; nb++) {
                MMA16816(acc[0][nb], ah0_0, ah0_1, ah0_2, ah0_3, bfr[nb][0], bfr[nb][1]);
                MMA16816(acc[1][nb], ah1_0, ah1_1, ah1_2, ah1_3, bfr[nb][0], bfr[nb][1]);
            }
        }

        // ---- epilogue: add t, dense store out[128*g + col] ----
        {
            const float* tsp = ts0 + (i & 1) * 1024;
            const int g0 = tile * 128;
            const int mb = g0 / 25;
            #pragma unroll
            for (int a2 = 0; a2 < 2; a2++) {
                #pragma unroll
                for (int half = 0; half < 2; half++) {
                    const int r = rbase + a2 * 16 + half * 8 + rl;
                    const int g = g0 + r;
                    if (g < G_TOTAL) {
                        const int toff = (g / 25 - mb) * 128;
                        float* dst = out + (size_t)g * 128;
                        #pragma unroll
                        for (int nb = 0; nb < 4; nb++) {
                            const int col = cbase + nb * 8 + cl;
                            float2 o2;
                            o2.x = acc[a2][nb][2 * half]     + tsp[toff + col];
                            o2.y = acc[a2][nb][2 * half + 1] + tsp[toff + col + 1];
                            *(float2*)(dst + col) = o2;
                        }
                    }
                }
            }
        }
        __syncthreads();                  // protect A/ts until all warps done
    }
}

// ---------------------------------------------------------------------------
extern "C" void kernel_launch(void* const* d_in, const int* in_sizes, int n_in,
                              void* d_out, int out_size)
{
    (void)in_sizes; (void)n_in; (void)out_size;
    const float* feat_f0 = (const float*)d_in[0];
    const float* feat_f1 = (const float*)d_in[1];
    const float* feat_c0 = (const float*)d_in[2];
    const float* feat_c1 = (const float*)d_in[3];
    const int*   b_ids   = (const int*)d_in[4];
    const int*   i_ids   = (const int*)d_in[5];
    const int*   j_ids   = (const int*)d_in[6];
    const float* Wd      = (const float*)d_in[7];
    const float* bd      = (const float*)d_in[8];
    const float* Wm      = (const float*)d_in[9];
    const float* bm      = (const float*)d_in[10];
    float* out = (float*)d_out;

    const size_t smemW = 128 * 129 * sizeof(float);
    const size_t smemP = 8192 + 32768 + PTILE * sizeof(float*);
    const size_t smemF = SMEM_FINE;

    cudaFuncSetAttribute(wc_kernel,   cudaFuncAttributeMaxDynamicSharedMemorySize, (int)smemW);
    cudaFuncSetAttribute(proj_kernel, cudaFuncAttributeMaxDynamicSharedMemorySize, (int)smemP);
    cudaFuncSetAttribute(fine_kernel, cudaFuncAttributeMaxDynamicSharedMemorySize, (int)smemF);

    warmup_kernel<<<1, 32>>>();
    wc_kernel<<<128, 128, smemW>>>(Wd, bd, Wm, bm);
    proj_kernel<<<NPTILES, 256, smemP>>>(feat_c0, feat_c1, b_ids, i_ids, j_ids);
    fine_kernel<<<148, 512, smemF>>>(feat_f0, feat_f1, b_ids, i_ids, j_ids, Wm, out);
}